// round 9
// baseline (speedup 1.0000x reference)
#include <cuda_runtime.h>
#include <cuda_bf16.h>

// Bidirectional linear RNN (units=1, linear, no bias), B=T=4096, scalar k,r.
//   fw_t = k*x_t + r*fw_{t-1};  bw_t = k*x_t + r*bw_{t+1}
// d_out = [stateless (B*T*2) | diff (B*T*2 zeros)], fw/bw interleaved.
//
// Round-8 structure (best measured: __stwt write-through outputs) with ONE
// change: __launch_bounds__(256, 6) to force regs<=40 -> 6 CTAs/SM.
//
// Grid 6144, interleaved 2:1 -> 4096 RNN blocks + 2048 zero-fill blocks.
// RNN block: 256 thr x 16 elems in regs; q=r^16 uniform -> warp shfl scan +
// 8-aggregate fold; 3 block barriers.

#define BB      4096
#define TT      4096
#define THREADS 256
#define CHUNK   16
#define NWARP   (THREADS / 32)

__global__ __launch_bounds__(THREADS, 6) void birnn_kernel(
    const float* __restrict__ x,
    const float* __restrict__ kp,
    const float* __restrict__ rp,
    float* __restrict__ out)
{
    __shared__ float sbuf[8448];      // x (padded 1/16) then out staging (1/32)
    __shared__ float Af[NWARP];
    __shared__ float Ab[NWARP];

    const int z  = blockIdx.x;
    const int m3 = z % 3;
    const int tid = threadIdx.x;

    float* const diffBase = out + (size_t)BB * TT * 2;

    if (m3 == 2) {
        // ---------- pure streaming zero-fill block ----------
        const int seg = z / 3;                      // 0..2047
        float4* dst = (float4*)diffBase + (size_t)seg * 4096;
        const float4 z4 = make_float4(0.f, 0.f, 0.f, 0.f);
        #pragma unroll 4
        for (int m = tid; m < 4096; m += THREADS)
            __stwt(dst + m, z4);
        return;
    }

    // ---------- RNN block ----------
    const int b    = (z / 3) * 2 + m3;              // row 0..4095
    const int lane = tid & 31;
    const int w    = tid >> 5;
    const float k  = *kp;
    const float r  = *rp;

    // q = r^16, Q = q^32 = r^512
    float q = r * r; q = q * q; q = q * q; q = q * q;
    float Q = q;
    #pragma unroll
    for (int i = 0; i < 5; i++) Q = Q * Q;

    // Coalesced load of row into padded smem (plain loads: keep x L2-resident)
    const float4* xrow = (const float4*)(x + (size_t)b * TT);
    #pragma unroll
    for (int i = tid; i < TT / 4; i += THREADS) {
        float4 v = xrow[i];
        int idx = 4 * i;
        int p = idx + (idx >> 4);
        sbuf[p + 0] = v.x; sbuf[p + 1] = v.y;
        sbuf[p + 2] = v.z; sbuf[p + 3] = v.w;
    }
    __syncthreads();                                 // B1

    // My 16 consecutive elements (bank-conflict-free, stride 17)
    float xv[CHUNK];
    {
        int p = tid * 17;
        #pragma unroll
        for (int j = 0; j < CHUNK; j++) xv[j] = sbuf[p + j];
    }

    // Local chunk scans from zero state
    float bL = 0.f, bR = 0.f;
    #pragma unroll
    for (int j = 0; j < CHUNK; j++) bL = fmaf(r, bL, k * xv[j]);
    #pragma unroll
    for (int j = CHUNK - 1; j >= 0; j--) bR = fmaf(r, bR, k * xv[j]);

    // Warp-level first-order scans (factor q), fw ascending / bw descending
    float vf = bL, vb = bR, qd = q;
    #pragma unroll
    for (int d = 1; d < 32; d <<= 1) {
        float of = __shfl_up_sync(0xffffffffu, vf, d);
        float ob = __shfl_down_sync(0xffffffffu, vb, d);
        if (lane >= d)     vf = fmaf(qd, of, vf);
        if (lane + d < 32) vb = fmaf(qd, ob, vb);
        qd *= qd;
    }
    if (lane == 31) Af[w] = vf;
    if (lane == 0)  Ab[w] = vb;
    __syncthreads();                                 // B2

    // Fold warp aggregates (factor Q) -> exclusive prefixes
    float Ef = 0.f;
    #pragma unroll
    for (int u = 0; u < NWARP; u++)
        if (u < w) Ef = fmaf(Q, Ef, Af[u]);
    float Eb = 0.f;
    #pragma unroll
    for (int u = NWARP - 1; u >= 0; u--)
        if (u > w) Eb = fmaf(Q, Eb, Ab[u]);

    // q^lane and q^(31-lane)
    float pwf = 1.f, pwb = 1.f, t = q;
    #pragma unroll
    for (int bit = 0; bit < 5; bit++) {
        if (lane & (1 << bit))        pwf *= t;
        if ((31 - lane) & (1 << bit)) pwb *= t;
        t *= t;
    }

    float hfp = __shfl_up_sync(0xffffffffu, vf, 1);   // h_{c-1}
    float hbn = __shfl_down_sync(0xffffffffu, vb, 1); // h'_{c+1}
    const float seedF = (lane > 0)  ? fmaf(pwf, Ef, hfp) : Ef;
    const float seedB = (lane < 31) ? fmaf(pwb, Eb, hbn) : Eb;

    // Recompute with seeds, stage interleaved (fw,bw) pairs (stride 33)
    {
        int p = tid * 33;
        float h = seedF;
        #pragma unroll
        for (int j = 0; j < CHUNK; j++) {
            h = fmaf(r, h, k * xv[j]);
            sbuf[p + 2 * j] = h;
        }
        float hb = seedB;
        #pragma unroll
        for (int j = CHUNK - 1; j >= 0; j--) {
            hb = fmaf(r, hb, k * xv[j]);
            sbuf[p + 2 * j + 1] = hb;
        }
    }
    __syncthreads();                                 // B3

    // Coalesced write-through writeback of the stateless row
    float4* orow = (float4*)(out + (size_t)b * (2 * TT));
    #pragma unroll
    for (int m = tid; m < (2 * TT) / 4; m += THREADS) {
        int idx = 4 * m;
        int p = idx + (idx >> 5);
        float4 v = make_float4(sbuf[p], sbuf[p + 1], sbuf[p + 2], sbuf[p + 3]);
        __stwt(orow + m, v);
    }
}

extern "C" void kernel_launch(void* const* d_in, const int* in_sizes, int n_in,
                              void* d_out, int out_size)
{
    const float* x  = (const float*)d_in[0];
    const float* kp = (const float*)d_in[1];
    const float* rp = (const float*)d_in[2];
    float* out = (float*)d_out;
    birnn_kernel<<<BB + BB / 2, THREADS>>>(x, kp, rp, out);
}

// round 10
// speedup vs baseline: 1.0253x; 1.0253x over previous
#include <cuda_runtime.h>
#include <cuda_bf16.h>

// Bidirectional linear RNN (units=1, linear, no bias), B=T=4096, scalar k,r.
//   fw_t = k*x_t + r*fw_{t-1};  bw_t = k*x_t + r*bw_{t+1}
// d_out = [stateless (B*T*2) | diff (B*T*2 zeros)], fw/bw interleaved.
//
// FROZEN Round-8 configuration (best measured: 50.5us kernel, 5475 GB/s):
//  - grid 6144 interleaved 2:1 -> 4096 RNN blocks + 2048 zero-fill blocks
//  - 256 thr x 16 elems in regs; q=r^16 uniform -> warp shfl scan + fold
//  - __stwt write-through outputs (L2 left entirely to x)
//  - NO launch-bounds occupancy clamp (48 regs / 5 CTAs/SM measured optimal;
//    forcing 40 regs or persistent grids both regressed)
// Only delta vs R8: zero-fill loop fully unrolled (16 front-batched stores).

#define BB      4096
#define TT      4096
#define THREADS 256
#define CHUNK   16
#define NWARP   (THREADS / 32)

__global__ __launch_bounds__(THREADS) void birnn_kernel(
    const float* __restrict__ x,
    const float* __restrict__ kp,
    const float* __restrict__ rp,
    float* __restrict__ out)
{
    __shared__ float sbuf[8448];      // x (padded 1/16) then out staging (1/32)
    __shared__ float Af[NWARP];
    __shared__ float Ab[NWARP];

    const int z  = blockIdx.x;
    const int m3 = z % 3;
    const int tid = threadIdx.x;

    float* const diffBase = out + (size_t)BB * TT * 2;

    if (m3 == 2) {
        // ---------- pure streaming zero-fill block (16 batched stores) ----------
        const int seg = z / 3;                      // 0..2047
        float4* dst = (float4*)diffBase + (size_t)seg * 4096 + tid;
        const float4 z4 = make_float4(0.f, 0.f, 0.f, 0.f);
        #pragma unroll
        for (int j = 0; j < 16; j++)
            __stwt(dst + j * THREADS, z4);
        return;
    }

    // ---------- RNN block ----------
    const int b    = (z / 3) * 2 + m3;              // row 0..4095
    const int lane = tid & 31;
    const int w    = tid >> 5;
    const float k  = *kp;
    const float r  = *rp;

    // q = r^16, Q = q^32 = r^512
    float q = r * r; q = q * q; q = q * q; q = q * q;
    float Q = q;
    #pragma unroll
    for (int i = 0; i < 5; i++) Q = Q * Q;

    // Coalesced load of row into padded smem (plain loads: keep x L2-resident)
    const float4* xrow = (const float4*)(x + (size_t)b * TT);
    #pragma unroll
    for (int i = tid; i < TT / 4; i += THREADS) {
        float4 v = xrow[i];
        int idx = 4 * i;
        int p = idx + (idx >> 4);
        sbuf[p + 0] = v.x; sbuf[p + 1] = v.y;
        sbuf[p + 2] = v.z; sbuf[p + 3] = v.w;
    }
    __syncthreads();                                 // B1

    // My 16 consecutive elements (bank-conflict-free, stride 17)
    float xv[CHUNK];
    {
        int p = tid * 17;
        #pragma unroll
        for (int j = 0; j < CHUNK; j++) xv[j] = sbuf[p + j];
    }

    // Local chunk scans from zero state
    float bL = 0.f, bR = 0.f;
    #pragma unroll
    for (int j = 0; j < CHUNK; j++) bL = fmaf(r, bL, k * xv[j]);
    #pragma unroll
    for (int j = CHUNK - 1; j >= 0; j--) bR = fmaf(r, bR, k * xv[j]);

    // Warp-level first-order scans (factor q), fw ascending / bw descending
    float vf = bL, vb = bR, qd = q;
    #pragma unroll
    for (int d = 1; d < 32; d <<= 1) {
        float of = __shfl_up_sync(0xffffffffu, vf, d);
        float ob = __shfl_down_sync(0xffffffffu, vb, d);
        if (lane >= d)     vf = fmaf(qd, of, vf);
        if (lane + d < 32) vb = fmaf(qd, ob, vb);
        qd *= qd;
    }
    if (lane == 31) Af[w] = vf;
    if (lane == 0)  Ab[w] = vb;
    __syncthreads();                                 // B2

    // Fold warp aggregates (factor Q) -> exclusive prefixes
    float Ef = 0.f;
    #pragma unroll
    for (int u = 0; u < NWARP; u++)
        if (u < w) Ef = fmaf(Q, Ef, Af[u]);
    float Eb = 0.f;
    #pragma unroll
    for (int u = NWARP - 1; u >= 0; u--)
        if (u > w) Eb = fmaf(Q, Eb, Ab[u]);

    // q^lane and q^(31-lane)
    float pwf = 1.f, pwb = 1.f, t = q;
    #pragma unroll
    for (int bit = 0; bit < 5; bit++) {
        if (lane & (1 << bit))        pwf *= t;
        if ((31 - lane) & (1 << bit)) pwb *= t;
        t *= t;
    }

    float hfp = __shfl_up_sync(0xffffffffu, vf, 1);   // h_{c-1}
    float hbn = __shfl_down_sync(0xffffffffu, vb, 1); // h'_{c+1}
    const float seedF = (lane > 0)  ? fmaf(pwf, Ef, hfp) : Ef;
    const float seedB = (lane < 31) ? fmaf(pwb, Eb, hbn) : Eb;

    // Recompute with seeds, stage interleaved (fw,bw) pairs (stride 33)
    {
        int p = tid * 33;
        float h = seedF;
        #pragma unroll
        for (int j = 0; j < CHUNK; j++) {
            h = fmaf(r, h, k * xv[j]);
            sbuf[p + 2 * j] = h;
        }
        float hb = seedB;
        #pragma unroll
        for (int j = CHUNK - 1; j >= 0; j--) {
            hb = fmaf(r, hb, k * xv[j]);
            sbuf[p + 2 * j + 1] = hb;
        }
    }
    __syncthreads();                                 // B3

    // Coalesced write-through writeback of the stateless row
    float4* orow = (float4*)(out + (size_t)b * (2 * TT));
    #pragma unroll
    for (int m = tid; m < (2 * TT) / 4; m += THREADS) {
        int idx = 4 * m;
        int p = idx + (idx >> 5);
        float4 v = make_float4(sbuf[p], sbuf[p + 1], sbuf[p + 2], sbuf[p + 3]);
        __stwt(orow + m, v);
    }
}

extern "C" void kernel_launch(void* const* d_in, const int* in_sizes, int n_in,
                              void* d_out, int out_size)
{
    const float* x  = (const float*)d_in[0];
    const float* kp = (const float*)d_in[1];
    const float* rp = (const float*)d_in[2];
    float* out = (float*)d_out;
    birnn_kernel<<<BB + BB / 2, THREADS>>>(x, kp, rp, out);
}

// round 11
// speedup vs baseline: 1.0757x; 1.0491x over previous
#include <cuda_runtime.h>
#include <cuda_bf16.h>

// Bidirectional linear RNN (units=1, linear, no bias), B=T=4096, scalar k,r.
//   fw_t = k*x_t + r*fw_{t-1};  bw_t = k*x_t + r*bw_{t+1}
// d_out = [stateless (B*T*2) | diff (B*T*2 zeros)], fw/bw interleaved.
//
// FINAL: exact Round-8 configuration (best measured: 50.5us kernel,
// 5475 GB/s, regs=48 / 5 CTAs/SM):
//  - grid 6144 interleaved 2:1 -> 4096 RNN blocks + 2048 zero-fill blocks
//  - 256 thr x 16 elems in regs; q=r^16 uniform -> warp shfl scan + fold
//  - __stwt write-through outputs (L2 left entirely to x)
//  - no launch-bounds clamp and no zero-loop unroll: both perturb ptxas
//    into a 40-reg schedule with worse load/store batching (R9/R10: +3-7us)

#define BB      4096
#define TT      4096
#define THREADS 256
#define CHUNK   16
#define NWARP   (THREADS / 32)

__global__ __launch_bounds__(THREADS) void birnn_kernel(
    const float* __restrict__ x,
    const float* __restrict__ kp,
    const float* __restrict__ rp,
    float* __restrict__ out)
{
    __shared__ float sbuf[8448];      // x (padded 1/16) then out staging (1/32)
    __shared__ float Af[NWARP];
    __shared__ float Ab[NWARP];

    const int z  = blockIdx.x;
    const int m3 = z % 3;
    const int tid = threadIdx.x;

    float* const diffBase = out + (size_t)BB * TT * 2;

    if (m3 == 2) {
        // ---------- pure streaming zero-fill block ----------
        const int seg = z / 3;                      // 0..2047
        float4* dst = (float4*)diffBase + (size_t)seg * 4096;
        const float4 z4 = make_float4(0.f, 0.f, 0.f, 0.f);
        #pragma unroll 4
        for (int m = tid; m < 4096; m += THREADS)
            __stwt(dst + m, z4);
        return;
    }

    // ---------- RNN block ----------
    const int b    = (z / 3) * 2 + m3;              // row 0..4095
    const int lane = tid & 31;
    const int w    = tid >> 5;
    const float k  = *kp;
    const float r  = *rp;

    // q = r^16, Q = q^32 = r^512
    float q = r * r; q = q * q; q = q * q; q = q * q;
    float Q = q;
    #pragma unroll
    for (int i = 0; i < 5; i++) Q = Q * Q;

    // Coalesced load of row into padded smem (plain loads: keep x L2-resident)
    const float4* xrow = (const float4*)(x + (size_t)b * TT);
    #pragma unroll
    for (int i = tid; i < TT / 4; i += THREADS) {
        float4 v = xrow[i];
        int idx = 4 * i;
        int p = idx + (idx >> 4);
        sbuf[p + 0] = v.x; sbuf[p + 1] = v.y;
        sbuf[p + 2] = v.z; sbuf[p + 3] = v.w;
    }
    __syncthreads();                                 // B1

    // My 16 consecutive elements (bank-conflict-free, stride 17)
    float xv[CHUNK];
    {
        int p = tid * 17;
        #pragma unroll
        for (int j = 0; j < CHUNK; j++) xv[j] = sbuf[p + j];
    }

    // Local chunk scans from zero state
    float bL = 0.f, bR = 0.f;
    #pragma unroll
    for (int j = 0; j < CHUNK; j++) bL = fmaf(r, bL, k * xv[j]);
    #pragma unroll
    for (int j = CHUNK - 1; j >= 0; j--) bR = fmaf(r, bR, k * xv[j]);

    // Warp-level first-order scans (factor q), fw ascending / bw descending
    float vf = bL, vb = bR, qd = q;
    #pragma unroll
    for (int d = 1; d < 32; d <<= 1) {
        float of = __shfl_up_sync(0xffffffffu, vf, d);
        float ob = __shfl_down_sync(0xffffffffu, vb, d);
        if (lane >= d)     vf = fmaf(qd, of, vf);
        if (lane + d < 32) vb = fmaf(qd, ob, vb);
        qd *= qd;
    }
    if (lane == 31) Af[w] = vf;
    if (lane == 0)  Ab[w] = vb;
    __syncthreads();                                 // B2

    // Fold warp aggregates (factor Q) -> exclusive prefixes
    float Ef = 0.f;
    #pragma unroll
    for (int u = 0; u < NWARP; u++)
        if (u < w) Ef = fmaf(Q, Ef, Af[u]);
    float Eb = 0.f;
    #pragma unroll
    for (int u = NWARP - 1; u >= 0; u--)
        if (u > w) Eb = fmaf(Q, Eb, Ab[u]);

    // q^lane and q^(31-lane)
    float pwf = 1.f, pwb = 1.f, t = q;
    #pragma unroll
    for (int bit = 0; bit < 5; bit++) {
        if (lane & (1 << bit))        pwf *= t;
        if ((31 - lane) & (1 << bit)) pwb *= t;
        t *= t;
    }

    float hfp = __shfl_up_sync(0xffffffffu, vf, 1);   // h_{c-1}
    float hbn = __shfl_down_sync(0xffffffffu, vb, 1); // h'_{c+1}
    const float seedF = (lane > 0)  ? fmaf(pwf, Ef, hfp) : Ef;
    const float seedB = (lane < 31) ? fmaf(pwb, Eb, hbn) : Eb;

    // Recompute with seeds, stage interleaved (fw,bw) pairs (stride 33)
    {
        int p = tid * 33;
        float h = seedF;
        #pragma unroll
        for (int j = 0; j < CHUNK; j++) {
            h = fmaf(r, h, k * xv[j]);
            sbuf[p + 2 * j] = h;
        }
        float hb = seedB;
        #pragma unroll
        for (int j = CHUNK - 1; j >= 0; j--) {
            hb = fmaf(r, hb, k * xv[j]);
            sbuf[p + 2 * j + 1] = hb;
        }
    }
    __syncthreads();                                 // B3

    // Coalesced write-through writeback of the stateless row
    float4* orow = (float4*)(out + (size_t)b * (2 * TT));
    #pragma unroll
    for (int m = tid; m < (2 * TT) / 4; m += THREADS) {
        int idx = 4 * m;
        int p = idx + (idx >> 5);
        float4 v = make_float4(sbuf[p], sbuf[p + 1], sbuf[p + 2], sbuf[p + 3]);
        __stwt(orow + m, v);
    }
}

extern "C" void kernel_launch(void* const* d_in, const int* in_sizes, int n_in,
                              void* d_out, int out_size)
{
    const float* x  = (const float*)d_in[0];
    const float* kp = (const float*)d_in[1];
    const float* rp = (const float*)d_in[2];
    float* out = (float*)d_out;
    birnn_kernel<<<BB + BB / 2, THREADS>>>(x, kp, rp, out);
}

// round 13
// speedup vs baseline: 1.0763x; 1.0006x over previous
#include <cuda_runtime.h>
#include <cuda_bf16.h>

// Bidirectional linear RNN (units=1, linear, no bias), B=T=4096, scalar k,r.
//   fw_t = k*x_t + r*fw_{t-1};  bw_t = k*x_t + r*bw_{t+1}
// d_out = [stateless (B*T*2) | diff (B*T*2 zeros)], fw/bw interleaved.
//
// Round-8 configuration (best measured: __stwt write-through outputs,
// 48-reg schedule, 5 CTAs/SM) with ONE change: finer filler interleave.
// Grid 8192, strict 1:1 alternation -> 4096 RNN blocks + 4096 zero-fill
// blocks of HALF the previous size (2048 float4 each), so store-only work
// mixes twice as finely across SMs/time and covers RNN prologue gaps.

#define BB      4096
#define TT      4096
#define THREADS 256
#define CHUNK   16
#define NWARP   (THREADS / 32)

__global__ __launch_bounds__(THREADS) void birnn_kernel(
    const float* __restrict__ x,
    const float* __restrict__ kp,
    const float* __restrict__ rp,
    float* __restrict__ out)
{
    __shared__ float sbuf[8448];      // x (padded 1/16) then out staging (1/32)
    __shared__ float Af[NWARP];
    __shared__ float Ab[NWARP];

    const int z  = blockIdx.x;
    const int tid = threadIdx.x;

    float* const diffBase = out + (size_t)BB * TT * 2;

    if (z & 1) {
        // ---------- pure streaming zero-fill block (half-row quantum) ----------
        const int seg = z >> 1;                     // 0..4095
        float4* dst = (float4*)diffBase + (size_t)seg * 2048;
        const float4 z4 = make_float4(0.f, 0.f, 0.f, 0.f);
        #pragma unroll 4
        for (int m = tid; m < 2048; m += THREADS)
            __stwt(dst + m, z4);
        return;
    }

    // ---------- RNN block ----------
    const int b    = z >> 1;                        // row 0..4095
    const int lane = tid & 31;
    const int w    = tid >> 5;
    const float k  = *kp;
    const float r  = *rp;

    // q = r^16, Q = q^32 = r^512
    float q = r * r; q = q * q; q = q * q; q = q * q;
    float Q = q;
    #pragma unroll
    for (int i = 0; i < 5; i++) Q = Q * Q;

    // Coalesced load of row into padded smem (plain loads: keep x L2-resident)
    const float4* xrow = (const float4*)(x + (size_t)b * TT);
    #pragma unroll
    for (int i = tid; i < TT / 4; i += THREADS) {
        float4 v = xrow[i];
        int idx = 4 * i;
        int p = idx + (idx >> 4);
        sbuf[p + 0] = v.x; sbuf[p + 1] = v.y;
        sbuf[p + 2] = v.z; sbuf[p + 3] = v.w;
    }
    __syncthreads();                                 // B1

    // My 16 consecutive elements (bank-conflict-free, stride 17)
    float xv[CHUNK];
    {
        int p = tid * 17;
        #pragma unroll
        for (int j = 0; j < CHUNK; j++) xv[j] = sbuf[p + j];
    }

    // Local chunk scans from zero state
    float bL = 0.f, bR = 0.f;
    #pragma unroll
    for (int j = 0; j < CHUNK; j++) bL = fmaf(r, bL, k * xv[j]);
    #pragma unroll
    for (int j = CHUNK - 1; j >= 0; j--) bR = fmaf(r, bR, k * xv[j]);

    // Warp-level first-order scans (factor q), fw ascending / bw descending
    float vf = bL, vb = bR, qd = q;
    #pragma unroll
    for (int d = 1; d < 32; d <<= 1) {
        float of = __shfl_up_sync(0xffffffffu, vf, d);
        float ob = __shfl_down_sync(0xffffffffu, vb, d);
        if (lane >= d)     vf = fmaf(qd, of, vf);
        if (lane + d < 32) vb = fmaf(qd, ob, vb);
        qd *= qd;
    }
    if (lane == 31) Af[w] = vf;
    if (lane == 0)  Ab[w] = vb;
    __syncthreads();                                 // B2

    // Fold warp aggregates (factor Q) -> exclusive prefixes
    float Ef = 0.f;
    #pragma unroll
    for (int u = 0; u < NWARP; u++)
        if (u < w) Ef = fmaf(Q, Ef, Af[u]);
    float Eb = 0.f;
    #pragma unroll
    for (int u = NWARP - 1; u >= 0; u--)
        if (u > w) Eb = fmaf(Q, Eb, Ab[u]);

    // q^lane and q^(31-lane)
    float pwf = 1.f, pwb = 1.f, t = q;
    #pragma unroll
    for (int bit = 0; bit < 5; bit++) {
        if (lane & (1 << bit))        pwf *= t;
        if ((31 - lane) & (1 << bit)) pwb *= t;
        t *= t;
    }

    float hfp = __shfl_up_sync(0xffffffffu, vf, 1);   // h_{c-1}
    float hbn = __shfl_down_sync(0xffffffffu, vb, 1); // h'_{c+1}
    const float seedF = (lane > 0)  ? fmaf(pwf, Ef, hfp) : Ef;
    const float seedB = (lane < 31) ? fmaf(pwb, Eb, hbn) : Eb;

    // Recompute with seeds, stage interleaved (fw,bw) pairs (stride 33)
    {
        int p = tid * 33;
        float h = seedF;
        #pragma unroll
        for (int j = 0; j < CHUNK; j++) {
            h = fmaf(r, h, k * xv[j]);
            sbuf[p + 2 * j] = h;
        }
        float hb = seedB;
        #pragma unroll
        for (int j = CHUNK - 1; j >= 0; j--) {
            hb = fmaf(r, hb, k * xv[j]);
            sbuf[p + 2 * j + 1] = hb;
        }
    }
    __syncthreads();                                 // B3

    // Coalesced write-through writeback of the stateless row
    float4* orow = (float4*)(out + (size_t)b * (2 * TT));
    #pragma unroll
    for (int m = tid; m < (2 * TT) / 4; m += THREADS) {
        int idx = 4 * m;
        int p = idx + (idx >> 5);
        float4 v = make_float4(sbuf[p], sbuf[p + 1], sbuf[p + 2], sbuf[p + 3]);
        __stwt(orow + m, v);
    }
}

extern "C" void kernel_launch(void* const* d_in, const int* in_sizes, int n_in,
                              void* d_out, int out_size)
{
    const float* x  = (const float*)d_in[0];
    const float* kp = (const float*)d_in[1];
    const float* rp = (const float*)d_in[2];
    float* out = (float*)d_out;
    birnn_kernel<<<2 * BB, THREADS>>>(x, kp, rp, out);
}